// round 13
// baseline (speedup 1.0000x reference)
#include <cuda_runtime.h>
#include <cuda_bf16.h>
#include <math.h>
#include <stdint.h>

#define NF   512
#define TOK  196
#define EMB  2560
#define HID  512
#define BK 32
#define ASTR 40                  // smem row stride in bf16 (32 + 8 pad)

// W1 half: 5 K-splits of 512; gram half: 2 K-splits of 1280
#define W1SPL 5
#define W1NST (512 / BK)         // 16
#define GRSPL 2
#define GRNST (1280 / BK)        // 40
#define NCTA_W1 (W1SPL * 32)     // 160
#define NCTA_GR (GRSPL * 32)     // 64

#define WCONV_BLKS ((EMB / 32) * (HID / 32))   // 1280
#define TVEC_BLKS  (HID / 64)                  // 8

// ---------------- scratch (device globals) ----------------------------------
__device__ __nv_bfloat16 g_Ahi[NF * EMB];     // layernormed pooled, bf16 hi
__device__ __nv_bfloat16 g_Alo[NF * EMB];     // residual lo
__device__ __nv_bfloat16 g_Whi[HID * EMB];    // W1_bot^T bf16 hi  [n][k]
__device__ __nv_bfloat16 g_Wlo[HID * EMB];    // W1_bot^T residual lo
__device__ float         g_inv[NF];
__device__ float         g_tvec[HID];
__device__ float         g_EW[W1SPL * NF * HID];  // W1-half partials
__device__ float         g_EG[GRSPL * NF * NF];   // gram-half partials
__device__ float         g_gates[NF];
__device__ unsigned      g_mask[NF * 16];
__device__ int           g_done;                  // last-block counter (zero-init)

// ---------------- PTX helpers -------------------------------------------------
__device__ __forceinline__ uint32_t smem_u32(const void* p) {
    uint32_t a;
    asm("{ .reg .u64 t; cvta.to.shared.u64 t, %1; cvt.u32.u64 %0, t; }" : "=r"(a) : "l"(p));
    return a;
}
__device__ __forceinline__ void cpa16(uint32_t d, const void* s) {
    asm volatile("cp.async.cg.shared.global [%0], [%1], 16;" :: "r"(d), "l"(s));
}
#define CP_COMMIT() asm volatile("cp.async.commit_group;" ::: "memory")
template<int N>
__device__ __forceinline__ void cp_wait() {
    asm volatile("cp.async.wait_group %0;" :: "n"(N) : "memory");
}
__device__ __forceinline__ void mma16816(float* d, const uint32_t* a, const uint32_t* b) {
    asm volatile(
        "mma.sync.aligned.m16n8k16.row.col.f32.bf16.bf16.f32 "
        "{%0,%1,%2,%3}, {%4,%5,%6,%7}, {%8,%9}, {%0,%1,%2,%3};"
        : "+f"(d[0]), "+f"(d[1]), "+f"(d[2]), "+f"(d[3])
        : "r"(a[0]), "r"(a[1]), "r"(a[2]), "r"(a[3]), "r"(b[0]), "r"(b[1]));
}
__device__ __forceinline__ void ldsm_x4(uint32_t* r, uint32_t addr) {
    asm volatile("ldmatrix.sync.aligned.m8n8.x4.shared.b16 {%0,%1,%2,%3}, [%4];"
        : "=r"(r[0]), "=r"(r[1]), "=r"(r[2]), "=r"(r[3]) : "r"(addr));
}

// ---------------- helpers ------------------------------------------------------
template<int NW>
__device__ __forceinline__ float block_sum(float v, float* sh) {
    #pragma unroll
    for (int o = 16; o > 0; o >>= 1) v += __shfl_down_sync(0xffffffffu, v, o);
    if ((threadIdx.x & 31) == 0) sh[threadIdx.x >> 5] = v;
    __syncthreads();
    float tot = 0.f;
    #pragma unroll
    for (int i = 0; i < NW; i++) tot += sh[i];
    __syncthreads();
    return tot;
}

// ---------------- 1) ONE front launch: mean+LN | wconv | tvec --------------------
__global__ void __launch_bounds__(512) k_front(const float* __restrict__ img,
                                               const float* __restrict__ txt,
                                               const float* __restrict__ lng,
                                               const float* __restrict__ lnb,
                                               const float* __restrict__ tg,
                                               const float* __restrict__ tb,
                                               const float* __restrict__ W1) {
    __shared__ float smem[EMB + 512];
    int b   = blockIdx.x;
    int tid = threadIdx.x;

    if (b < NF) {
        float* sh = smem;
        int f = b;
        const float4* p4 = reinterpret_cast<const float4*>(img + (size_t)f * TOK * EMB);
        const float*  p1 = img + (size_t)f * TOK * EMB + 2048 + tid;
        float4 a4 = make_float4(0.f, 0.f, 0.f, 0.f);
        float  a1 = 0.f;
        #pragma unroll 4
        for (int t = 0; t < TOK; t++) {
            float4 x = p4[(size_t)t * 640 + tid];
            a4.x += x.x; a4.y += x.y; a4.z += x.z; a4.w += x.w;
            a1 += p1[(size_t)t * EMB];
        }
        const float sc = 1.0f / (float)TOK;
        float4 v4 = make_float4(a4.x * sc, a4.y * sc, a4.z * sc, a4.w * sc);
        float  v1 = a1 * sc;

        float s  = v4.x + v4.y + v4.z + v4.w + v1;
        float s2 = v4.x * v4.x + v4.y * v4.y + v4.z * v4.z + v4.w * v4.w + v1 * v1;
        float S  = block_sum<16>(s,  sh);
        float S2 = block_sum<16>(s2, sh);
        float mean = S * (1.0f / EMB);
        float var  = S2 * (1.0f / EMB) - mean * mean;
        float rstd = rsqrtf(var + 1e-5f);

        float vv[5] = {v4.x, v4.y, v4.z, v4.w, v1};
        int   ee[5] = {4 * tid, 4 * tid + 1, 4 * tid + 2, 4 * tid + 3, 2048 + tid};
        float y[5];
        float n2 = 0.f;
        #pragma unroll
        for (int i = 0; i < 5; i++) {
            y[i] = (vv[i] - mean) * rstd * lng[ee[i]] + lnb[ee[i]];
            n2 += y[i] * y[i];
        }
        __nv_bfloat16 hi[5];
        #pragma unroll
        for (int i = 0; i < 5; i++) hi[i] = __float2bfloat16(y[i]);
        __nv_bfloat16* dsth = g_Ahi + (size_t)f * EMB;
        __nv_bfloat16* dstl = g_Alo + (size_t)f * EMB;
        __nv_bfloat16 hv[4] = {hi[0], hi[1], hi[2], hi[3]};
        *reinterpret_cast<uint2*>(dsth + 4 * tid) = *reinterpret_cast<uint2*>(hv);
        __nv_bfloat16 lv[4];
        #pragma unroll
        for (int i = 0; i < 4; i++) lv[i] = __float2bfloat16(y[i] - __bfloat162float(hi[i]));
        *reinterpret_cast<uint2*>(dstl + 4 * tid) = *reinterpret_cast<uint2*>(lv);
        dsth[2048 + tid] = hi[4];
        dstl[2048 + tid] = __float2bfloat16(y[4] - __bfloat162float(hi[4]));
        float N2 = block_sum<16>(n2, sh);
        if (tid == 0) g_inv[f] = 1.0f / fmaxf(sqrtf(N2), 1e-8f);
    } else if (b < NF + WCONV_BLKS) {
        float (*t)[33] = reinterpret_cast<float(*)[33]>(smem);
        int bb = b - NF;
        const float* Wb = W1 + (size_t)EMB * HID;
        int k0 = (bb % (EMB / 32)) * 32;
        int n0 = (bb / (EMB / 32)) * 32;
        int tx = tid & 31, ty = tid >> 5;
        #pragma unroll
        for (int j = ty; j < 32; j += 16)
            t[j][tx] = Wb[(size_t)(k0 + j) * HID + n0 + tx];
        __syncthreads();
        #pragma unroll
        for (int j = ty; j < 32; j += 16) {
            float x = t[tx][j];
            __nv_bfloat16 hi = __float2bfloat16(x);
            g_Whi[(size_t)(n0 + j) * EMB + k0 + tx] = hi;
            g_Wlo[(size_t)(n0 + j) * EMB + k0 + tx] = __float2bfloat16(x - __bfloat162float(hi));
        }
    } else {
        float* st   = smem;            // txt_ln [2560]
        float* part = smem + EMB;      // [8][64]
        int hb = (b - NF - WCONV_BLKS) * 64;

        float v[5]; float s = 0.f, s2 = 0.f;
        #pragma unroll
        for (int i = 0; i < 5; i++) {
            v[i] = txt[tid + i * 512];
            s += v[i]; s2 += v[i] * v[i];
        }
        float* sh = part + 256;
        float S  = block_sum<16>(s,  sh);
        float S2 = block_sum<16>(s2, sh);
        float mean = S * (1.0f / EMB);
        float var  = S2 * (1.0f / EMB) - mean * mean;
        float rstd = rsqrtf(var + 1e-5f);
        #pragma unroll
        for (int i = 0; i < 5; i++) {
            int e = tid + i * 512;
            st[e] = (v[i] - mean) * rstd * tg[e] + tb[e];
        }
        __syncthreads();

        int h     = hb + (tid & 63);
        int chunk = tid >> 6;
        int kk0   = chunk * 320;
        float acc = 0.f;
        const float* w = W1 + (size_t)kk0 * HID + h;
        #pragma unroll 8
        for (int e = 0; e < 320; e++) acc = fmaf(st[kk0 + e], w[(size_t)e * HID], acc);
        part[chunk * 64 + (tid & 63)] = acc;
        __syncthreads();
        if (tid < 64) {
            float tot = 0.f;
            #pragma unroll
            for (int c = 0; c < 8; c++) tot += part[c * 64 + tid];
            g_tvec[hb + tid] = tot;
        }
    }
}

// ---------------- 2) HMMA GEMM, balanced flat grid -------------------------------
#define STG_SZ  30720
#define OFF_AHI(b) ((b) * STG_SZ)
#define OFF_ALO(b) ((b) * STG_SZ + 10240)
#define OFF_BHI(b) ((b) * STG_SZ + 20480)
#define OFF_BLO(b) ((b) * STG_SZ + 25600)
#define SM_TOT (2 * STG_SZ)

__device__ __forceinline__ void ld_tile(uint32_t sm, const __nv_bfloat16* g,
                                        int rows, int tid) {
    int nvec = rows * 4;
    for (int i = tid; i < nvec; i += 256) {
        int row = i >> 2, seg = i & 3;
        cpa16(sm + (uint32_t)(row * ASTR + seg * 8) * 2,
              g + (size_t)row * EMB + seg * 8);
    }
}

__global__ void __launch_bounds__(256, 2) k_gemm_mma() {
    extern __shared__ char smem[];
    uint32_t sbase = smem_u32(smem);
    int tid = threadIdx.x, wid = tid >> 5, lid = tid & 31;
    int bx = blockIdx.x;
    bool w1tile = (bx < NCTA_W1);

    int np, nstage, kbase, bn, bm;
    const __nv_bfloat16 *Bh, *Bl = nullptr;
    float* Eout;
    if (w1tile) {
        int ks = bx >> 5, r = bx & 31;
        bn = (r & 7) * 64;  bm = (r >> 3) * 128;
        kbase = ks * 512;   nstage = W1NST;  np = 3;
        Bh = g_Whi + (size_t)bn * EMB + kbase;
        Bl = g_Wlo + (size_t)bn * EMB + kbase;
        Eout = g_EW + (size_t)ks * NF * HID;
    } else {
        int b2 = bx - NCTA_W1;
        int ks = b2 >> 5, r = b2 & 31;
        bn = (r & 7) * 64;  bm = (r >> 3) * 128;
        kbase = ks * 1280;  nstage = GRNST;  np = 1;
        Bh = g_Ahi + (size_t)bn * EMB + kbase;
        Eout = g_EG + (size_t)ks * NF * NF;
    }
    const __nv_bfloat16* Ah = g_Ahi + (size_t)bm * EMB + kbase;
    const __nv_bfloat16* Al = g_Alo + (size_t)bm * EMB + kbase;

    int wm = wid & 3;
    int wn = wid >> 2;
    int g  = lid >> 2;
    int t  = lid & 3;

    uint32_t aoff = (uint32_t)((wm * 32 + (lid & 15)) * ASTR + (lid >> 4) * 8) * 2;
    uint32_t boff = (uint32_t)((wn * 32 + (lid & 7) + (lid >> 4) * 8) * ASTR
                               + ((lid >> 3) & 1) * 8) * 2;

    float acc[2][4][4];
    #pragma unroll
    for (int i = 0; i < 2; i++)
        #pragma unroll
        for (int j = 0; j < 4; j++)
            #pragma unroll
            for (int r = 0; r < 4; r++) acc[i][j][r] = 0.f;

    ld_tile(sbase + OFF_AHI(0), Ah, 128, tid);
    ld_tile(sbase + OFF_BHI(0), Bh, 64, tid);
    if (w1tile) {
        ld_tile(sbase + OFF_ALO(0), Al, 128, tid);
        ld_tile(sbase + OFF_BLO(0), Bl, 64, tid);
    }
    CP_COMMIT();

    for (int s = 0; s < nstage; s++) {
        int buf = s & 1;
        if (s + 1 < nstage) {
            int nb = buf ^ 1;
            ld_tile(sbase + OFF_AHI(nb), Ah + (s + 1) * BK, 128, tid);
            ld_tile(sbase + OFF_BHI(nb), Bh + (s + 1) * BK, 64, tid);
            if (w1tile) {
                ld_tile(sbase + OFF_ALO(nb), Al + (s + 1) * BK, 128, tid);
                ld_tile(sbase + OFF_BLO(nb), Bl + (s + 1) * BK, 64, tid);
            }
            CP_COMMIT();
            cp_wait<1>();
        } else {
            cp_wait<0>();
        }
        __syncthreads();

        for (int p = 0; p < np; p++) {
            uint32_t Asm = sbase + ((p == 2) ? OFF_ALO(buf) : OFF_AHI(buf));
            uint32_t Bsm = sbase + ((p == 1) ? OFF_BLO(buf) : OFF_BHI(buf));
            // batch ALL fragment loads for both kk chunks (8 LDSM in flight)
            uint32_t af[2][2][4], bfm[2][2][4];
            #pragma unroll
            for (int kk2 = 0; kk2 < 2; kk2++) {
                ldsm_x4(af[kk2][0],  Asm + aoff + kk2 * 32);
                ldsm_x4(af[kk2][1],  Asm + aoff + 16 * ASTR * 2 + kk2 * 32);
                ldsm_x4(bfm[kk2][0], Bsm + boff + kk2 * 32);
                ldsm_x4(bfm[kk2][1], Bsm + boff + 16 * ASTR * 2 + kk2 * 32);
            }
            #pragma unroll
            for (int kk2 = 0; kk2 < 2; kk2++)
                #pragma unroll
                for (int mi = 0; mi < 2; mi++)
                    #pragma unroll
                    for (int ni = 0; ni < 4; ni++)
                        mma16816(acc[mi][ni], af[kk2][mi],
                                 &bfm[kk2][ni >> 1][(ni & 1) * 2]);
        }
        __syncthreads();
    }

    #pragma unroll
    for (int mi = 0; mi < 2; mi++) {
        #pragma unroll
        for (int ni = 0; ni < 4; ni++) {
            int r0 = bm + wm * 32 + mi * 16 + g;
            int c  = bn + wn * 32 + ni * 8 + 2 * t;
            *(float2*)&Eout[(size_t)r0 * 512 + c]       = make_float2(acc[mi][ni][0], acc[mi][ni][1]);
            *(float2*)&Eout[(size_t)(r0 + 8) * 512 + c] = make_float2(acc[mi][ni][2], acc[mi][ni][3]);
        }
    }
}

// ---------------- 3) gates + f2f bitmask + last-block greedy selection -----------
__global__ void __launch_bounds__(256) k_gates(const float* __restrict__ b1,
                                               const float* __restrict__ W2,
                                               const float* __restrict__ b2,
                                               float* __restrict__ out,
                                               int out_size) {
    __shared__ float sh[8];
    int f   = blockIdx.x;
    int tid = threadIdx.x;
    const size_t PW = (size_t)NF * HID;
    const size_t PG = (size_t)NF * NF;

    float s = 0.f;
    #pragma unroll
    for (int h = tid; h < HID; h += 256) {
        size_t idx = (size_t)f * HID + h;
        float v = g_EW[idx] + g_EW[idx + PW] + g_EW[idx + 2 * PW]
                + g_EW[idx + 3 * PW] + g_EW[idx + 4 * PW]
                + g_tvec[h] + b1[h];
        s += fmaxf(v, 0.f) * W2[h];
    }
    float tot = block_sum<8>(s, sh);
    if (tid == 0) g_gates[f] = 1.0f / (1.0f + expf(-(tot + b2[0])));

    float invi = g_inv[f];
    #pragma unroll
    for (int j = tid; j < NF; j += 256) {
        size_t idx = (size_t)f * NF + j;
        float d = g_EG[idx] + g_EG[idx + PG];
        float c = d * invi * g_inv[j];
        unsigned bal = __ballot_sync(0xffffffffu, c > 0.98f);
        if ((j & 31) == 0) g_mask[f * 16 + (j >> 5)] = bal;
    }

    // ---- last-block selection ----
    __threadfence();
    __syncthreads();
    __shared__ int slast;
    if (tid == 0) slast = (atomicAdd(&g_done, 1) == NF - 1) ? 1 : 0;
    __syncthreads();
    if (!slast) return;
    __threadfence();

    __shared__ unsigned smask[NF * 16];    // 32 KB
    __shared__ float    sg[NF];
    __shared__ unsigned ssel16[32];
    #pragma unroll
    for (int i = 0; i < 32; i++) smask[tid + i * 256] = g_mask[tid + i * 256];
    sg[tid]       = g_gates[tid];
    sg[tid + 256] = g_gates[tid + 256];
    if (tid == 0) g_done = 0;              // reset for next graph replay
    __syncthreads();

    if (tid < 32) {
        int l = tid;                       // lane owns frames [16l, 16l+16)
        float gr[16];
        #pragma unroll
        for (int j = 0; j < 16; j++) gr[j] = sg[l * 16 + j];
        unsigned vis = 0, sel = 0;

        for (int it = 0; it < 32; it++) {
            // local argmax over unvisited (strict > keeps lowest local index on tie)
            float bv = 0.f; int bj = 0;
            #pragma unroll
            for (int j = 0; j < 16; j++) {
                bool ok = !((vis >> j) & 1u) && gr[j] > bv;
                if (ok) { bv = gr[j]; bj = j; }
            }
            // packed key: high bits = gate (positive float, monotone as u32,
            // truncated below bit 9), low 9 bits = 511 - global index
            // (max key == max gate, then min index; matches stable argsort(-g))
            unsigned vb  = __float_as_uint(bv);
            unsigned key = (vb == 0u) ? 0u
                         : ((vb & 0xFFFFFE00u) | (511u - (unsigned)(l * 16 + bj)));
            unsigned kmax = __reduce_max_sync(0xffffffffu, key);
            if (kmax == 0u) break;         // all visited
            unsigned idx = 511u - (kmax & 0x1FFu);
            if ((idx >> 4) == (unsigned)l) sel |= 1u << (idx & 15u);
            unsigned w = smask[idx * 16 + (l >> 1)];
            vis |= (w >> ((l & 1) * 16)) & 0xFFFFu;
        }
        ssel16[l] = sel;
    }
    __syncthreads();

    #pragma unroll
    for (int q = 0; q < 2; q++) {
        int fr = tid + q * 256;
        unsigned sbits = ssel16[fr >> 4];
        float selv = (float)((sbits >> (fr & 15)) & 1u);
        if (fr < out_size)      out[fr]      = selv;
        if (NF + fr < out_size) out[NF + fr] = sg[fr];
    }
}

// ---------------- launch -----------------------------------------------------------
extern "C" void kernel_launch(void* const* d_in, const int* in_sizes, int n_in,
                              void* d_out, int out_size) {
    const float* img    = (const float*)d_in[0];
    const float* txt    = (const float*)d_in[1];
    const float* ln_t_g = (const float*)d_in[2];
    const float* ln_t_b = (const float*)d_in[3];
    const float* ln_l_g = (const float*)d_in[4];
    const float* ln_l_b = (const float*)d_in[5];
    const float* W1     = (const float*)d_in[6];
    const float* b1     = (const float*)d_in[7];
    const float* W2     = (const float*)d_in[8];
    const float* b2     = (const float*)d_in[9];
    float* out = (float*)d_out;

    cudaFuncSetAttribute(k_gemm_mma, cudaFuncAttributeMaxDynamicSharedMemorySize, SM_TOT);

    k_front<<<NF + WCONV_BLKS + TVEC_BLKS, 512>>>(img, txt, ln_l_g, ln_l_b,
                                                  ln_t_g, ln_t_b, W1);
    k_gemm_mma<<<NCTA_W1 + NCTA_GR, 256, SM_TOT>>>();
    k_gates<<<NF, 256>>>(b1, W2, b2, out, out_size);
}

// round 14
// speedup vs baseline: 1.0339x; 1.0339x over previous
#include <cuda_runtime.h>
#include <cuda_bf16.h>
#include <math.h>
#include <stdint.h>

#define NF   512
#define TOK  196
#define EMB  2560
#define HID  512
#define BK 32
#define ASTR 40                  // smem row stride in bf16 (32 + 8 pad)

// W1 half: 5 K-splits of 512; gram half: 2 K-splits of 1280
#define W1SPL 5
#define W1NST (512 / BK)         // 16
#define GRSPL 2
#define GRNST (1280 / BK)        // 40
#define NCTA_W1 (W1SPL * 32)     // 160
#define NCTA_GR (GRSPL * 32)     // 64

#define WCONV_BLKS ((EMB / 32) * (HID / 32))   // 1280
#define TVEC_BLKS  (HID / 64)                  // 8

// ---------------- scratch (device globals) ----------------------------------
__device__ __nv_bfloat16 g_Ahi[NF * EMB];     // layernormed pooled, bf16 hi
__device__ __nv_bfloat16 g_Alo[NF * EMB];     // residual lo
__device__ __nv_bfloat16 g_Whi[HID * EMB];    // W1_bot^T bf16 hi  [n][k]
__device__ __nv_bfloat16 g_Wlo[HID * EMB];    // W1_bot^T residual lo
__device__ float         g_inv[NF];
__device__ float         g_tvec[HID];
__device__ float         g_EW[W1SPL * NF * HID];  // W1-half partials
__device__ float         g_EG[GRSPL * NF * NF];   // gram-half partials
__device__ float         g_gates[NF];
__device__ unsigned      g_mask[NF * 16];

// ---------------- PTX helpers -------------------------------------------------
__device__ __forceinline__ uint32_t smem_u32(const void* p) {
    uint32_t a;
    asm("{ .reg .u64 t; cvta.to.shared.u64 t, %1; cvt.u32.u64 %0, t; }" : "=r"(a) : "l"(p));
    return a;
}
__device__ __forceinline__ void cpa16(uint32_t d, const void* s) {
    asm volatile("cp.async.cg.shared.global [%0], [%1], 16;" :: "r"(d), "l"(s));
}
#define CP_COMMIT() asm volatile("cp.async.commit_group;" ::: "memory")
template<int N>
__device__ __forceinline__ void cp_wait() {
    asm volatile("cp.async.wait_group %0;" :: "n"(N) : "memory");
}
__device__ __forceinline__ void mma16816(float* d, const uint32_t* a, const uint32_t* b) {
    asm volatile(
        "mma.sync.aligned.m16n8k16.row.col.f32.bf16.bf16.f32 "
        "{%0,%1,%2,%3}, {%4,%5,%6,%7}, {%8,%9}, {%0,%1,%2,%3};"
        : "+f"(d[0]), "+f"(d[1]), "+f"(d[2]), "+f"(d[3])
        : "r"(a[0]), "r"(a[1]), "r"(a[2]), "r"(a[3]), "r"(b[0]), "r"(b[1]));
}
__device__ __forceinline__ void ldsm_x4(uint32_t* r, uint32_t addr) {
    asm volatile("ldmatrix.sync.aligned.m8n8.x4.shared.b16 {%0,%1,%2,%3}, [%4];"
        : "=r"(r[0]), "=r"(r[1]), "=r"(r[2]), "=r"(r[3]) : "r"(addr));
}
__device__ __forceinline__ float4 ldcs4(const float4* p) {
    float4 v;
    asm volatile("ld.global.cs.v4.f32 {%0,%1,%2,%3}, [%4];"
        : "=f"(v.x), "=f"(v.y), "=f"(v.z), "=f"(v.w) : "l"(p));
    return v;
}
__device__ __forceinline__ float ldcs1(const float* p) {
    float v;
    asm volatile("ld.global.cs.f32 %0, [%1];" : "=f"(v) : "l"(p));
    return v;
}

// ---------------- helpers ------------------------------------------------------
template<int NW>
__device__ __forceinline__ float block_sum(float v, float* sh) {
    #pragma unroll
    for (int o = 16; o > 0; o >>= 1) v += __shfl_down_sync(0xffffffffu, v, o);
    if ((threadIdx.x & 31) == 0) sh[threadIdx.x >> 5] = v;
    __syncthreads();
    float tot = 0.f;
    #pragma unroll
    for (int i = 0; i < NW; i++) tot += sh[i];
    __syncthreads();
    return tot;
}

// ---------------- 1) ONE front launch: mean+LN | wconv | tvec --------------------
__global__ void __launch_bounds__(512) k_front(const float* __restrict__ img,
                                               const float* __restrict__ txt,
                                               const float* __restrict__ lng,
                                               const float* __restrict__ lnb,
                                               const float* __restrict__ tg,
                                               const float* __restrict__ tb,
                                               const float* __restrict__ W1) {
    __shared__ float smem[EMB + 512];
    int b   = blockIdx.x;
    int tid = threadIdx.x;

    if (b < NF) {
        float* sh = smem;
        int f = b;
        const float4* p4 = reinterpret_cast<const float4*>(img + (size_t)f * TOK * EMB);
        const float*  p1 = img + (size_t)f * TOK * EMB + 2048 + tid;
        float4 a4 = make_float4(0.f, 0.f, 0.f, 0.f);
        float  a1 = 0.f;
        #pragma unroll 4
        for (int t = 0; t < TOK; t++) {
            float4 x = ldcs4(p4 + (size_t)t * 640 + tid);
            a4.x += x.x; a4.y += x.y; a4.z += x.z; a4.w += x.w;
            a1 += ldcs1(p1 + (size_t)t * EMB);
        }
        const float sc = 1.0f / (float)TOK;
        float4 v4 = make_float4(a4.x * sc, a4.y * sc, a4.z * sc, a4.w * sc);
        float  v1 = a1 * sc;

        float s  = v4.x + v4.y + v4.z + v4.w + v1;
        float s2 = v4.x * v4.x + v4.y * v4.y + v4.z * v4.z + v4.w * v4.w + v1 * v1;
        float S  = block_sum<16>(s,  sh);
        float S2 = block_sum<16>(s2, sh);
        float mean = S * (1.0f / EMB);
        float var  = S2 * (1.0f / EMB) - mean * mean;
        float rstd = rsqrtf(var + 1e-5f);

        float vv[5] = {v4.x, v4.y, v4.z, v4.w, v1};
        int   ee[5] = {4 * tid, 4 * tid + 1, 4 * tid + 2, 4 * tid + 3, 2048 + tid};
        float y[5];
        float n2 = 0.f;
        #pragma unroll
        for (int i = 0; i < 5; i++) {
            y[i] = (vv[i] - mean) * rstd * lng[ee[i]] + lnb[ee[i]];
            n2 += y[i] * y[i];
        }
        __nv_bfloat16 hi[5];
        #pragma unroll
        for (int i = 0; i < 5; i++) hi[i] = __float2bfloat16(y[i]);
        __nv_bfloat16* dsth = g_Ahi + (size_t)f * EMB;
        __nv_bfloat16* dstl = g_Alo + (size_t)f * EMB;
        __nv_bfloat16 hv[4] = {hi[0], hi[1], hi[2], hi[3]};
        *reinterpret_cast<uint2*>(dsth + 4 * tid) = *reinterpret_cast<uint2*>(hv);
        __nv_bfloat16 lv[4];
        #pragma unroll
        for (int i = 0; i < 4; i++) lv[i] = __float2bfloat16(y[i] - __bfloat162float(hi[i]));
        *reinterpret_cast<uint2*>(dstl + 4 * tid) = *reinterpret_cast<uint2*>(lv);
        dsth[2048 + tid] = hi[4];
        dstl[2048 + tid] = __float2bfloat16(y[4] - __bfloat162float(hi[4]));
        float N2 = block_sum<16>(n2, sh);
        if (tid == 0) g_inv[f] = 1.0f / fmaxf(sqrtf(N2), 1e-8f);
    } else if (b < NF + WCONV_BLKS) {
        float (*t)[33] = reinterpret_cast<float(*)[33]>(smem);
        int bb = b - NF;
        const float* Wb = W1 + (size_t)EMB * HID;
        int k0 = (bb % (EMB / 32)) * 32;
        int n0 = (bb / (EMB / 32)) * 32;
        int tx = tid & 31, ty = tid >> 5;
        #pragma unroll
        for (int j = ty; j < 32; j += 16)
            t[j][tx] = Wb[(size_t)(k0 + j) * HID + n0 + tx];
        __syncthreads();
        #pragma unroll
        for (int j = ty; j < 32; j += 16) {
            float x = t[tx][j];
            __nv_bfloat16 hi = __float2bfloat16(x);
            g_Whi[(size_t)(n0 + j) * EMB + k0 + tx] = hi;
            g_Wlo[(size_t)(n0 + j) * EMB + k0 + tx] = __float2bfloat16(x - __bfloat162float(hi));
        }
    } else {
        float* st   = smem;            // txt_ln [2560]
        float* part = smem + EMB;      // [8][64]
        int hb = (b - NF - WCONV_BLKS) * 64;

        float v[5]; float s = 0.f, s2 = 0.f;
        #pragma unroll
        for (int i = 0; i < 5; i++) {
            v[i] = txt[tid + i * 512];
            s += v[i]; s2 += v[i] * v[i];
        }
        float* sh = part + 256;
        float S  = block_sum<16>(s,  sh);
        float S2 = block_sum<16>(s2, sh);
        float mean = S * (1.0f / EMB);
        float var  = S2 * (1.0f / EMB) - mean * mean;
        float rstd = rsqrtf(var + 1e-5f);
        #pragma unroll
        for (int i = 0; i < 5; i++) {
            int e = tid + i * 512;
            st[e] = (v[i] - mean) * rstd * tg[e] + tb[e];
        }
        __syncthreads();

        int h     = hb + (tid & 63);
        int chunk = tid >> 6;
        int kk0   = chunk * 320;
        float acc = 0.f;
        const float* w = W1 + (size_t)kk0 * HID + h;
        #pragma unroll 8
        for (int e = 0; e < 320; e++) acc = fmaf(st[kk0 + e], w[(size_t)e * HID], acc);
        part[chunk * 64 + (tid & 63)] = acc;
        __syncthreads();
        if (tid < 64) {
            float tot = 0.f;
            #pragma unroll
            for (int c = 0; c < 8; c++) tot += part[c * 64 + tid];
            g_tvec[hb + tid] = tot;
        }
    }
}

// ---------------- 2) HMMA GEMM, balanced flat grid -------------------------------
#define STG_SZ  30720
#define OFF_AHI(b) ((b) * STG_SZ)
#define OFF_ALO(b) ((b) * STG_SZ + 10240)
#define OFF_BHI(b) ((b) * STG_SZ + 20480)
#define OFF_BLO(b) ((b) * STG_SZ + 25600)
#define SM_TOT (2 * STG_SZ)

__device__ __forceinline__ void ld_tile(uint32_t sm, const __nv_bfloat16* g,
                                        int rows, int tid) {
    int nvec = rows * 4;
    for (int i = tid; i < nvec; i += 256) {
        int row = i >> 2, seg = i & 3;
        cpa16(sm + (uint32_t)(row * ASTR + seg * 8) * 2,
              g + (size_t)row * EMB + seg * 8);
    }
}

__global__ void __launch_bounds__(256, 2) k_gemm_mma() {
    extern __shared__ char smem[];
    uint32_t sbase = smem_u32(smem);
    int tid = threadIdx.x, wid = tid >> 5, lid = tid & 31;
    int bx = blockIdx.x;
    bool w1tile = (bx < NCTA_W1);

    int np, nstage, kbase, bn, bm;
    const __nv_bfloat16 *Bh, *Bl = nullptr;
    float* Eout;
    if (w1tile) {
        int ks = bx >> 5, r = bx & 31;
        bn = (r & 7) * 64;  bm = (r >> 3) * 128;
        kbase = ks * 512;   nstage = W1NST;  np = 3;
        Bh = g_Whi + (size_t)bn * EMB + kbase;
        Bl = g_Wlo + (size_t)bn * EMB + kbase;
        Eout = g_EW + (size_t)ks * NF * HID;
    } else {
        int b2 = bx - NCTA_W1;
        int ks = b2 >> 5, r = b2 & 31;
        bn = (r & 7) * 64;  bm = (r >> 3) * 128;
        kbase = ks * 1280;  nstage = GRNST;  np = 1;
        Bh = g_Ahi + (size_t)bn * EMB + kbase;
        Eout = g_EG + (size_t)ks * NF * NF;
    }
    const __nv_bfloat16* Ah = g_Ahi + (size_t)bm * EMB + kbase;
    const __nv_bfloat16* Al = g_Alo + (size_t)bm * EMB + kbase;

    int wm = wid & 3;
    int wn = wid >> 2;
    int g  = lid >> 2;
    int t  = lid & 3;

    uint32_t aoff = (uint32_t)((wm * 32 + (lid & 15)) * ASTR + (lid >> 4) * 8) * 2;
    uint32_t boff = (uint32_t)((wn * 32 + (lid & 7) + (lid >> 4) * 8) * ASTR
                               + ((lid >> 3) & 1) * 8) * 2;

    float acc[2][4][4];
    #pragma unroll
    for (int i = 0; i < 2; i++)
        #pragma unroll
        for (int j = 0; j < 4; j++)
            #pragma unroll
            for (int r = 0; r < 4; r++) acc[i][j][r] = 0.f;

    ld_tile(sbase + OFF_AHI(0), Ah, 128, tid);
    ld_tile(sbase + OFF_BHI(0), Bh, 64, tid);
    if (w1tile) {
        ld_tile(sbase + OFF_ALO(0), Al, 128, tid);
        ld_tile(sbase + OFF_BLO(0), Bl, 64, tid);
    }
    CP_COMMIT();

    for (int s = 0; s < nstage; s++) {
        int buf = s & 1;
        if (s + 1 < nstage) {
            int nb = buf ^ 1;
            ld_tile(sbase + OFF_AHI(nb), Ah + (s + 1) * BK, 128, tid);
            ld_tile(sbase + OFF_BHI(nb), Bh + (s + 1) * BK, 64, tid);
            if (w1tile) {
                ld_tile(sbase + OFF_ALO(nb), Al + (s + 1) * BK, 128, tid);
                ld_tile(sbase + OFF_BLO(nb), Bl + (s + 1) * BK, 64, tid);
            }
            CP_COMMIT();
            cp_wait<1>();
        } else {
            cp_wait<0>();
        }
        __syncthreads();

        for (int p = 0; p < np; p++) {
            uint32_t Asm = sbase + ((p == 2) ? OFF_ALO(buf) : OFF_AHI(buf));
            uint32_t Bsm = sbase + ((p == 1) ? OFF_BLO(buf) : OFF_BHI(buf));
            // batch ALL fragment loads for both kk chunks (8 LDSM in flight)
            uint32_t af[2][2][4], bfm[2][2][4];
            #pragma unroll
            for (int kk2 = 0; kk2 < 2; kk2++) {
                ldsm_x4(af[kk2][0],  Asm + aoff + kk2 * 32);
                ldsm_x4(af[kk2][1],  Asm + aoff + 16 * ASTR * 2 + kk2 * 32);
                ldsm_x4(bfm[kk2][0], Bsm + boff + kk2 * 32);
                ldsm_x4(bfm[kk2][1], Bsm + boff + 16 * ASTR * 2 + kk2 * 32);
            }
            #pragma unroll
            for (int kk2 = 0; kk2 < 2; kk2++)
                #pragma unroll
                for (int mi = 0; mi < 2; mi++)
                    #pragma unroll
                    for (int ni = 0; ni < 4; ni++)
                        mma16816(acc[mi][ni], af[kk2][mi],
                                 &bfm[kk2][ni >> 1][(ni & 1) * 2]);
        }
        __syncthreads();
    }

    #pragma unroll
    for (int mi = 0; mi < 2; mi++) {
        #pragma unroll
        for (int ni = 0; ni < 4; ni++) {
            int r0 = bm + wm * 32 + mi * 16 + g;
            int c  = bn + wn * 32 + ni * 8 + 2 * t;
            *(float2*)&Eout[(size_t)r0 * 512 + c]       = make_float2(acc[mi][ni][0], acc[mi][ni][1]);
            *(float2*)&Eout[(size_t)(r0 + 8) * 512 + c] = make_float2(acc[mi][ni][2], acc[mi][ni][3]);
        }
    }
}

// ---------------- 3) gates + f2f bitmask (256 threads) ----------------------------
__global__ void __launch_bounds__(256) k_gates(const float* __restrict__ b1,
                                               const float* __restrict__ W2,
                                               const float* __restrict__ b2) {
    __shared__ float sh[8];
    int f   = blockIdx.x;
    int tid = threadIdx.x;
    const size_t PW = (size_t)NF * HID;
    const size_t PG = (size_t)NF * NF;

    float s = 0.f;
    #pragma unroll
    for (int h = tid; h < HID; h += 256) {
        size_t idx = (size_t)f * HID + h;
        float v = g_EW[idx] + g_EW[idx + PW] + g_EW[idx + 2 * PW]
                + g_EW[idx + 3 * PW] + g_EW[idx + 4 * PW]
                + g_tvec[h] + b1[h];
        s += fmaxf(v, 0.f) * W2[h];
    }
    float tot = block_sum<8>(s, sh);
    if (tid == 0) g_gates[f] = 1.0f / (1.0f + expf(-(tot + b2[0])));

    float invi = g_inv[f];
    #pragma unroll
    for (int j = tid; j < NF; j += 256) {
        size_t idx = (size_t)f * NF + j;
        float d = g_EG[idx] + g_EG[idx + PG];
        float c = d * invi * g_inv[j];
        unsigned bal = __ballot_sync(0xffffffffu, c > 0.98f);
        if ((j & 31) == 0) g_mask[f * 16 + (j >> 5)] = bal;
    }
}

// ---------------- 4) greedy selection: single warp + packed-key redux -------------
__global__ void __launch_bounds__(512) k_select(float* __restrict__ out, int out_size) {
    __shared__ unsigned smask[NF * 16];    // 32 KB
    __shared__ float    sg[NF];
    __shared__ unsigned ssel16[32];
    int tid = threadIdx.x;

    #pragma unroll
    for (int i = 0; i < 16; i++) smask[tid + i * 512] = g_mask[tid + i * 512];
    sg[tid] = g_gates[tid];
    __syncthreads();

    if (tid < 32) {
        int l = tid;                       // lane owns frames [16l, 16l+16)
        float gr[16];
        #pragma unroll
        for (int j = 0; j < 16; j++) gr[j] = sg[l * 16 + j];
        unsigned vis = 0, sel = 0;

        for (int it = 0; it < 32; it++) {
            // local argmax over unvisited (strict > keeps lowest local index on tie)
            float bv = 0.f; int bj = 0;
            #pragma unroll
            for (int j = 0; j < 16; j++) {
                bool ok = !((vis >> j) & 1u) && gr[j] > bv;
                if (ok) { bv = gr[j]; bj = j; }
            }
            // packed key: high bits = gate (positive float, monotone as u32,
            // truncated below bit 9), low 9 bits = 511 - global index
            // (max key == max gate, then min index; matches stable argsort(-g))
            unsigned vb  = __float_as_uint(bv);
            unsigned key = (vb == 0u) ? 0u
                         : ((vb & 0xFFFFFE00u) | (511u - (unsigned)(l * 16 + bj)));
            unsigned kmax = __reduce_max_sync(0xffffffffu, key);
            if (kmax == 0u) break;         // all visited
            unsigned idx = 511u - (kmax & 0x1FFu);
            if ((idx >> 4) == (unsigned)l) sel |= 1u << (idx & 15u);
            unsigned w = smask[idx * 16 + (l >> 1)];
            vis |= (w >> ((l & 1) * 16)) & 0xFFFFu;
        }
        ssel16[l] = sel;
    }
    __syncthreads();

    unsigned s = ssel16[tid >> 4];
    float selv = (float)((s >> (tid & 15)) & 1u);
    if (tid < out_size)      out[tid]      = selv;
    if (NF + tid < out_size) out[NF + tid] = sg[tid];
}

// ---------------- launch -----------------------------------------------------------
extern "C" void kernel_launch(void* const* d_in, const int* in_sizes, int n_in,
                              void* d_out, int out_size) {
    const float* img    = (const float*)d_in[0];
    const float* txt    = (const float*)d_in[1];
    const float* ln_t_g = (const float*)d_in[2];
    const float* ln_t_b = (const float*)d_in[3];
    const float* ln_l_g = (const float*)d_in[4];
    const float* ln_l_b = (const float*)d_in[5];
    const float* W1     = (const float*)d_in[6];
    const float* b1     = (const float*)d_in[7];
    const float* W2     = (const float*)d_in[8];
    const float* b2     = (const float*)d_in[9];
    float* out = (float*)d_out;

    cudaFuncSetAttribute(k_gemm_mma, cudaFuncAttributeMaxDynamicSharedMemorySize, SM_TOT);

    k_front<<<NF + WCONV_BLKS + TVEC_BLKS, 512>>>(img, txt, ln_l_g, ln_l_b,
                                                  ln_t_g, ln_t_b, W1);
    k_gemm_mma<<<NCTA_W1 + NCTA_GR, 256, SM_TOT>>>();
    k_gates<<<NF, 256>>>(b1, W2, b2);
    k_select<<<1, 512>>>(out, out_size);
}